// round 5
// baseline (speedup 1.0000x reference)
#include <cuda_runtime.h>
#include <stdint.h>

#define C 64
#define MAXN 100000

// Aggregation buffer: agg[n][:] = sum_{e: row=n} w_e * x[col_e][:]
// (device global: no allocs allowed in kernel_launch)
__device__ float g_agg[(size_t)MAXN * C];

// ---------------------------------------------------------------------------
// Zero the aggregation buffer (float4 stores).
// ---------------------------------------------------------------------------
__global__ void __launch_bounds__(256)
zero_agg_kernel(int total4) {
    int i = blockIdx.x * blockDim.x + threadIdx.x;
    if (i < total4)
        reinterpret_cast<float4*>(g_agg)[i] = make_float4(0.f, 0.f, 0.f, 0.f);
}

// ---------------------------------------------------------------------------
// Edge scatter on RAW x (R4 winning shape: 16 lanes/edge, coalesced 256B row
// gather, v4 RED, 2 independent edges per thread for MLP).
//   agg[row][:] += edge_weight * x[col][:]
// edge_index is int32 on device (JAX x64 disabled downcasts int64).
// ---------------------------------------------------------------------------
__global__ void __launch_bounds__(256)
scatter_kernel(const int* __restrict__ ei,
               const float* __restrict__ ew,
               const float* __restrict__ x,
               int E, int H) {
    long long t = (long long)blockIdx.x * blockDim.x + threadIdx.x;
    int e0 = (int)(t >> 4);
    if (e0 >= H) return;
    int lane = (int)t & 15;
    int e1 = e0 + H;
    bool has1 = (e1 < E);

    int dst0 = __ldg(ei + e0);
    int src0 = __ldg(ei + (size_t)E + e0);
    float w0 = __ldg(ew + e0);
    int dst1 = 0, src1 = 0;
    float w1 = 0.0f;
    if (has1) {
        dst1 = __ldg(ei + e1);
        src1 = __ldg(ei + (size_t)E + e1);
        w1 = __ldg(ew + e1);
    }

    float4 v0 = __ldg(reinterpret_cast<const float4*>(x + (size_t)src0 * C) + lane);
    float4 v1 = make_float4(0.f, 0.f, 0.f, 0.f);
    if (has1)
        v1 = __ldg(reinterpret_cast<const float4*>(x + (size_t)src1 * C) + lane);

    float4 r0 = make_float4(v0.x * w0, v0.y * w0, v0.z * w0, v0.w * w0);
    float* op0 = g_agg + (size_t)dst0 * C + (lane << 2);
    asm volatile("red.global.add.v4.f32 [%0], {%1, %2, %3, %4};"
                 :: "l"(op0), "f"(r0.x), "f"(r0.y), "f"(r0.z), "f"(r0.w)
                 : "memory");

    if (has1) {
        float4 r1 = make_float4(v1.x * w1, v1.y * w1, v1.z * w1, v1.w * w1);
        float* op1 = g_agg + (size_t)dst1 * C + (lane << 2);
        asm volatile("red.global.add.v4.f32 [%0], {%1, %2, %3, %4};"
                     :: "l"(op1), "f"(r1.x), "f"(r1.y), "f"(r1.z), "f"(r1.w)
                     : "memory");
    }
}

// ---------------------------------------------------------------------------
// GEMM pass 1 (side stream, overlaps with scatter):
//   out[n][:] = x[n][:] @ Ws^T + (bs + bn)
// One thread per node; x row in 16 float4 regs; Ws in shared (broadcast LDS).
// ---------------------------------------------------------------------------
__global__ void __launch_bounds__(128)
gemm_self_kernel(const float* __restrict__ x,
                 const float* __restrict__ Ws,
                 const float* __restrict__ bs,
                 const float* __restrict__ bn,
                 float* __restrict__ out,
                 int N) {
    __shared__ float sW[C * C];
    __shared__ float sb[C];

    int tid = threadIdx.x;
    for (int i = tid; i < C * C; i += blockDim.x) sW[i] = Ws[i];
    if (tid < C) sb[tid] = bs[tid] + bn[tid];
    __syncthreads();

    int n = blockIdx.x * blockDim.x + tid;
    if (n >= N) return;

    float4 xr[16];
    const float4* xp = reinterpret_cast<const float4*>(x + (size_t)n * C);
#pragma unroll
    for (int i = 0; i < 16; i++) xr[i] = xp[i];

    float4* op = reinterpret_cast<float4*>(out + (size_t)n * C);

#pragma unroll 1
    for (int jg = 0; jg < C; jg += 4) {
        float acc[4];
#pragma unroll
        for (int jj = 0; jj < 4; jj++) acc[jj] = sb[jg + jj];
#pragma unroll
        for (int k = 0; k < 16; k++) {
            float4 xv = xr[k];
#pragma unroll
            for (int jj = 0; jj < 4; jj++) {
                float4 w = *reinterpret_cast<const float4*>(&sW[(jg + jj) * C + k * 4]);
                acc[jj] = fmaf(xv.x, w.x, acc[jj]);
                acc[jj] = fmaf(xv.y, w.y, acc[jj]);
                acc[jj] = fmaf(xv.z, w.z, acc[jj]);
                acc[jj] = fmaf(xv.w, w.w, acc[jj]);
            }
        }
        op[jg >> 2] = make_float4(acc[0], acc[1], acc[2], acc[3]);
    }
}

// ---------------------------------------------------------------------------
// GEMM pass 2 (after scatter AND pass 1):
//   out[n][:] += agg[n][:] @ Wn^T
// ---------------------------------------------------------------------------
__global__ void __launch_bounds__(128)
gemm_neigh_kernel(const float* __restrict__ Wn,
                  float* __restrict__ out,
                  int N) {
    __shared__ float sW[C * C];

    int tid = threadIdx.x;
    for (int i = tid; i < C * C; i += blockDim.x) sW[i] = Wn[i];
    __syncthreads();

    int n = blockIdx.x * blockDim.x + tid;
    if (n >= N) return;

    float4 xr[16];
    const float4* ap = reinterpret_cast<const float4*>(g_agg + (size_t)n * C);
#pragma unroll
    for (int i = 0; i < 16; i++) xr[i] = ap[i];

    float4* op = reinterpret_cast<float4*>(out + (size_t)n * C);

#pragma unroll 1
    for (int jg = 0; jg < C; jg += 4) {
        float4 prev = op[jg >> 2];  // out from pass 1
        float acc[4] = {prev.x, prev.y, prev.z, prev.w};
#pragma unroll
        for (int k = 0; k < 16; k++) {
            float4 xv = xr[k];
#pragma unroll
            for (int jj = 0; jj < 4; jj++) {
                float4 w = *reinterpret_cast<const float4*>(&sW[(jg + jj) * C + k * 4]);
                acc[jj] = fmaf(xv.x, w.x, acc[jj]);
                acc[jj] = fmaf(xv.y, w.y, acc[jj]);
                acc[jj] = fmaf(xv.z, w.z, acc[jj]);
                acc[jj] = fmaf(xv.w, w.w, acc[jj]);
            }
        }
        op[jg >> 2] = make_float4(acc[0], acc[1], acc[2], acc[3]);
    }
}

// ---------------------------------------------------------------------------
// Inputs (metadata order): x[N*64] f32, edge_index[2*E] i32, edge_weight[E] f32,
// W_self[64*64] f32, b_self[64] f32, W_neigh[64*64] f32, b_neigh[64] f32,
// num_nodes (scalar, unused -- N derived from in_sizes[0]).
// Output: float32 [N*64].
//
// Fork-join: scatter chain (stream 0) runs concurrently with the FFMA-bound
// self-GEMM (side stream); the neigh-GEMM joins both. Side stream/events are
// created once on the first (uncaptured correctness) call; captured calls only
// issue record/wait, which become graph dependency edges.
// ---------------------------------------------------------------------------
extern "C" void kernel_launch(void* const* d_in, const int* in_sizes, int n_in,
                              void* d_out, int out_size) {
    const float* x  = (const float*)d_in[0];
    const int*   ei = (const int*)d_in[1];
    const float* ew = (const float*)d_in[2];
    const float* Ws = (const float*)d_in[3];
    const float* bs = (const float*)d_in[4];
    const float* Wn = (const float*)d_in[5];
    const float* bn = (const float*)d_in[6];
    float* out = (float*)d_out;

    int N = in_sizes[0] / C;
    int E = in_sizes[2];
    int H = (E + 1) / 2;

    static cudaStream_t s_side = nullptr;
    static cudaEvent_t ev_fork = nullptr, ev_join = nullptr;
    if (s_side == nullptr) {
        cudaStreamCreateWithFlags(&s_side, cudaStreamNonBlocking);
        cudaEventCreateWithFlags(&ev_fork, cudaEventDisableTiming);
        cudaEventCreateWithFlags(&ev_join, cudaEventDisableTiming);
    }

    // Fork: side stream branches off the main (captured) stream.
    cudaEventRecord(ev_fork, 0);
    cudaStreamWaitEvent(s_side, ev_fork, 0);

    // Side stream: out = x@Ws^T + (bs+bn)   [FFMA-bound]
    gemm_self_kernel<<<(N + 127) / 128, 128, 0, s_side>>>(x, Ws, bs, bn, out, N);
    cudaEventRecord(ev_join, s_side);

    // Main stream: agg = 0; agg[row] += w * x[col]   [memory-bound]
    int total4 = N * C / 4;
    zero_agg_kernel<<<(total4 + 255) / 256, 256>>>(total4);
    {
        long long total = (long long)H * 16;
        int blocks = (int)((total + 255) / 256);
        scatter_kernel<<<blocks, 256>>>(ei, ew, x, E, H);
    }

    // Join, then: out += agg@Wn^T
    cudaStreamWaitEvent(0, ev_join, 0);
    gemm_neigh_kernel<<<(N + 127) / 128, 128>>>(Wn, out, N);
}

// round 6
// speedup vs baseline: 1.2977x; 1.2977x over previous
#include <cuda_runtime.h>
#include <stdint.h>

#define C 64
#define MAXN 100000

#define TM 128      // nodes per block tile
#define KC 32       // k-chunk staged per phase
#define XS 129      // x_s row pitch (floats): pad for ~2-way staging conflicts
#define WS 68       // w_s row pitch (floats): keeps LDS.128 16B-aligned

// Aggregation buffer: agg[n][:] = sum_{e: row=n} w_e * x[col_e][:]
__device__ float g_agg[(size_t)MAXN * C];

// ---------------------------------------------------------------------------
// Zero the aggregation buffer (float4 stores).
// ---------------------------------------------------------------------------
__global__ void __launch_bounds__(256)
zero_agg_kernel(int total4) {
    int i = blockIdx.x * blockDim.x + threadIdx.x;
    if (i < total4)
        reinterpret_cast<float4*>(g_agg)[i] = make_float4(0.f, 0.f, 0.f, 0.f);
}

// ---------------------------------------------------------------------------
// Edge scatter (R4 winning shape: 16 lanes/edge, coalesced 256B row gather,
// v4 RED, 2 independent edges per thread for MLP).
//   agg[row][:] += edge_weight * x[col][:]
// edge_index is int32 on device (JAX x64 disabled downcasts int64).
// ---------------------------------------------------------------------------
__global__ void __launch_bounds__(256)
scatter_kernel(const int* __restrict__ ei,
               const float* __restrict__ ew,
               const float* __restrict__ x,
               int E, int H) {
    long long t = (long long)blockIdx.x * blockDim.x + threadIdx.x;
    int e0 = (int)(t >> 4);
    if (e0 >= H) return;
    int lane = (int)t & 15;
    int e1 = e0 + H;
    bool has1 = (e1 < E);

    int dst0 = __ldg(ei + e0);
    int src0 = __ldg(ei + (size_t)E + e0);
    float w0 = __ldg(ew + e0);
    int dst1 = 0, src1 = 0;
    float w1 = 0.0f;
    if (has1) {
        dst1 = __ldg(ei + e1);
        src1 = __ldg(ei + (size_t)E + e1);
        w1 = __ldg(ew + e1);
    }

    float4 v0 = __ldg(reinterpret_cast<const float4*>(x + (size_t)src0 * C) + lane);
    float4 v1 = make_float4(0.f, 0.f, 0.f, 0.f);
    if (has1)
        v1 = __ldg(reinterpret_cast<const float4*>(x + (size_t)src1 * C) + lane);

    float4 r0 = make_float4(v0.x * w0, v0.y * w0, v0.z * w0, v0.w * w0);
    float* op0 = g_agg + (size_t)dst0 * C + (lane << 2);
    asm volatile("red.global.add.v4.f32 [%0], {%1, %2, %3, %4};"
                 :: "l"(op0), "f"(r0.x), "f"(r0.y), "f"(r0.z), "f"(r0.w)
                 : "memory");

    if (has1) {
        float4 r1 = make_float4(v1.x * w1, v1.y * w1, v1.z * w1, v1.w * w1);
        float* op1 = g_agg + (size_t)dst1 * C + (lane << 2);
        asm volatile("red.global.add.v4.f32 [%0], {%1, %2, %3, %4};"
                     :: "l"(op1), "f"(r1.x), "f"(r1.y), "f"(r1.z), "f"(r1.w)
                     : "memory");
    }
}

// ---------------------------------------------------------------------------
// Tiled GEMM core: computes acc[2][4][4] for this thread's 8x4 micro-tile of
// src[TM rows x 64] @ W^T.  x_s: [KC][XS] transposed src tile; w_s: [KC][WS]
// transposed W. Per k: 8 broadcast scalar LDS (a) + 1 aligned LDS.128 (b)
// + 32 FFMA -> FFMA-pipe-bound.
// Thread map: tx = tid&15 -> cols 4tx..4tx+3; ty = tid>>4 -> rows {4ty+r,
// 64+4ty+r}.
// ---------------------------------------------------------------------------
__device__ __forceinline__ void gemm_tile_core(
    const float* __restrict__ src, const float* __restrict__ W,
    float* x_s, float* w_s, float acc[2][4][4],
    int m0, int N, int tid, int tx, int ty)
{
#pragma unroll 1
    for (int kc = 0; kc < 2; kc++) {
        __syncthreads();
        // Stage x chunk: TM rows x 32 k (transposed). Coalesced 16B loads.
#pragma unroll
        for (int it = 0; it < 4; it++) {
            int i = tid + it * 256;
            int m = i >> 3, q = i & 7;
            float4 v = make_float4(0.f, 0.f, 0.f, 0.f);
            if (m0 + m < N)
                v = reinterpret_cast<const float4*>(src)[(size_t)(m0 + m) * 16 + kc * 8 + q];
            x_s[(4 * q + 0) * XS + m] = v.x;
            x_s[(4 * q + 1) * XS + m] = v.y;
            x_s[(4 * q + 2) * XS + m] = v.z;
            x_s[(4 * q + 3) * XS + m] = v.w;
        }
        // Stage W chunk: 64 rows x 32 k (transposed).
#pragma unroll
        for (int it = 0; it < 2; it++) {
            int i = tid + it * 256;
            int j = i >> 3, q = i & 7;
            float4 v = reinterpret_cast<const float4*>(W)[j * 16 + kc * 8 + q];
            w_s[(4 * q + 0) * WS + j] = v.x;
            w_s[(4 * q + 1) * WS + j] = v.y;
            w_s[(4 * q + 2) * WS + j] = v.z;
            w_s[(4 * q + 3) * WS + j] = v.w;
        }
        __syncthreads();

#pragma unroll 8
        for (int k = 0; k < KC; k++) {
            float4 b = *reinterpret_cast<const float4*>(&w_s[k * WS + 4 * tx]);
            float a0[4], a1[4];
#pragma unroll
            for (int r = 0; r < 4; r++) {
                a0[r] = x_s[k * XS + 4 * ty + r];
                a1[r] = x_s[k * XS + 64 + 4 * ty + r];
            }
#pragma unroll
            for (int r = 0; r < 4; r++) {
                acc[0][r][0] = fmaf(a0[r], b.x, acc[0][r][0]);
                acc[0][r][1] = fmaf(a0[r], b.y, acc[0][r][1]);
                acc[0][r][2] = fmaf(a0[r], b.z, acc[0][r][2]);
                acc[0][r][3] = fmaf(a0[r], b.w, acc[0][r][3]);
                acc[1][r][0] = fmaf(a1[r], b.x, acc[1][r][0]);
                acc[1][r][1] = fmaf(a1[r], b.y, acc[1][r][1]);
                acc[1][r][2] = fmaf(a1[r], b.z, acc[1][r][2]);
                acc[1][r][3] = fmaf(a1[r], b.w, acc[1][r][3]);
            }
        }
    }
}

// ---------------------------------------------------------------------------
// GEMM pass 1 (side stream, overlaps with scatter):
//   out[tile] = x[tile] @ Ws^T + (bs + bn)
// ---------------------------------------------------------------------------
__global__ void __launch_bounds__(256)
gemm_self_kernel(const float* __restrict__ x,
                 const float* __restrict__ Ws,
                 const float* __restrict__ bs,
                 const float* __restrict__ bn,
                 float* __restrict__ out,
                 int N) {
    __shared__ float x_s[KC * XS];
    __shared__ float w_s[KC * WS];

    int tid = threadIdx.x;
    int tx = tid & 15, ty = tid >> 4;
    int m0 = blockIdx.x * TM;

    float acc[2][4][4];
#pragma unroll
    for (int h = 0; h < 2; h++)
#pragma unroll
        for (int r = 0; r < 4; r++)
#pragma unroll
            for (int s = 0; s < 4; s++) acc[h][r][s] = 0.f;

    gemm_tile_core(x, Ws, x_s, w_s, acc, m0, N, tid, tx, ty);

    float4 bias;
    bias.x = __ldg(bs + 4 * tx + 0) + __ldg(bn + 4 * tx + 0);
    bias.y = __ldg(bs + 4 * tx + 1) + __ldg(bn + 4 * tx + 1);
    bias.z = __ldg(bs + 4 * tx + 2) + __ldg(bn + 4 * tx + 2);
    bias.w = __ldg(bs + 4 * tx + 3) + __ldg(bn + 4 * tx + 3);

#pragma unroll
    for (int h = 0; h < 2; h++) {
#pragma unroll
        for (int r = 0; r < 4; r++) {
            int m = m0 + h * 64 + 4 * ty + r;
            if (m < N) {
                float4 o = make_float4(acc[h][r][0] + bias.x, acc[h][r][1] + bias.y,
                                       acc[h][r][2] + bias.z, acc[h][r][3] + bias.w);
                reinterpret_cast<float4*>(out)[(size_t)m * 16 + tx] = o;
            }
        }
    }
}

// ---------------------------------------------------------------------------
// GEMM pass 2 (after scatter AND pass 1):
//   out[tile] += agg[tile] @ Wn^T
// ---------------------------------------------------------------------------
__global__ void __launch_bounds__(256)
gemm_neigh_kernel(const float* __restrict__ Wn,
                  float* __restrict__ out,
                  int N) {
    __shared__ float x_s[KC * XS];
    __shared__ float w_s[KC * WS];

    int tid = threadIdx.x;
    int tx = tid & 15, ty = tid >> 4;
    int m0 = blockIdx.x * TM;

    float acc[2][4][4];
#pragma unroll
    for (int h = 0; h < 2; h++)
#pragma unroll
        for (int r = 0; r < 4; r++)
#pragma unroll
            for (int s = 0; s < 4; s++) acc[h][r][s] = 0.f;

    gemm_tile_core(g_agg, Wn, x_s, w_s, acc, m0, N, tid, tx, ty);

#pragma unroll
    for (int h = 0; h < 2; h++) {
#pragma unroll
        for (int r = 0; r < 4; r++) {
            int m = m0 + h * 64 + 4 * ty + r;
            if (m < N) {
                float4 prev = reinterpret_cast<const float4*>(out)[(size_t)m * 16 + tx];
                float4 o = make_float4(prev.x + acc[h][r][0], prev.y + acc[h][r][1],
                                       prev.z + acc[h][r][2], prev.w + acc[h][r][3]);
                reinterpret_cast<float4*>(out)[(size_t)m * 16 + tx] = o;
            }
        }
    }
}

// ---------------------------------------------------------------------------
// Inputs (metadata order): x[N*64] f32, edge_index[2*E] i32, edge_weight[E] f32,
// W_self[64*64] f32, b_self[64] f32, W_neigh[64*64] f32, b_neigh[64] f32,
// num_nodes (scalar, unused). Output: float32 [N*64].
//
// Fork-join: memory-bound scatter chain (stream 0) overlaps the FFMA-bound
// self-GEMM (side stream); the neigh-GEMM joins both.
// ---------------------------------------------------------------------------
extern "C" void kernel_launch(void* const* d_in, const int* in_sizes, int n_in,
                              void* d_out, int out_size) {
    const float* x  = (const float*)d_in[0];
    const int*   ei = (const int*)d_in[1];
    const float* ew = (const float*)d_in[2];
    const float* Ws = (const float*)d_in[3];
    const float* bs = (const float*)d_in[4];
    const float* Wn = (const float*)d_in[5];
    const float* bn = (const float*)d_in[6];
    float* out = (float*)d_out;

    int N = in_sizes[0] / C;
    int E = in_sizes[2];
    int H = (E + 1) / 2;
    int nTiles = (N + TM - 1) / TM;

    static cudaStream_t s_side = nullptr;
    static cudaEvent_t ev_fork = nullptr, ev_join = nullptr;
    if (s_side == nullptr) {
        cudaStreamCreateWithFlags(&s_side, cudaStreamNonBlocking);
        cudaEventCreateWithFlags(&ev_fork, cudaEventDisableTiming);
        cudaEventCreateWithFlags(&ev_join, cudaEventDisableTiming);
    }

    // Fork: side stream branches off the main (captured) stream.
    cudaEventRecord(ev_fork, 0);
    cudaStreamWaitEvent(s_side, ev_fork, 0);

    // Side stream: out = x@Ws^T + (bs+bn)   [FFMA-bound, hidden under scatter]
    gemm_self_kernel<<<nTiles, 256, 0, s_side>>>(x, Ws, bs, bn, out, N);
    cudaEventRecord(ev_join, s_side);

    // Main stream: agg = 0; agg[row] += w * x[col]   [memory/latency-bound]
    int total4 = N * C / 4;
    zero_agg_kernel<<<(total4 + 255) / 256, 256>>>(total4);
    {
        long long total = (long long)H * 16;
        int blocks = (int)((total + 255) / 256);
        scatter_kernel<<<blocks, 256>>>(ei, ew, x, E, H);
    }

    // Join, then: out += agg@Wn^T
    cudaStreamWaitEvent(0, ev_join, 0);
    gemm_neigh_kernel<<<nTiles, 256>>>(Wn, out, N);
}